// round 2
// baseline (speedup 1.0000x reference)
#include <cuda_runtime.h>
#include <math.h>

#define N_NODES 100000
#define F_IN    128
#define HID     64

// Combined (summed) K=1 diffusion weights, built once per launch by prep_kernel.
__device__ float g_Wz[F_IN * HID];
__device__ float g_Wh[F_IN * HID];

// Wz/Wh have shape (2, 1, 192, 64) row-major. Only channel rows 0..127 (the X
// half of cat([X, H0])) matter since H0 == 0. Effective weight = W[0,0]+W[1,0].
__global__ void prep_kernel(const float* __restrict__ Wz,
                            const float* __restrict__ Wh) {
    int idx = blockIdx.x * blockDim.x + threadIdx.x;
    if (idx < F_IN * HID) {
        int k = idx / HID;
        int j = idx % HID;
        int o0 = k * HID + j;                 // d = 0 slice
        int o1 = 192 * HID + k * HID + j;     // d = 1 slice
        g_Wz[idx] = Wz[o0] + Wz[o1];
        g_Wh[idx] = Wh[o0] + Wh[o1];
    }
}

// Tiled dual-GEMM + fused GRU epilogue.
// Block: 256 threads = 16x16; tile = 64 nodes x 64 hidden cols (all of HID).
// Each thread: 4 nodes x 4 cols x 2 matrices = 32 fp32 accumulators.
// Smem: both weight matrices (64 KB), transposed x tile (padded), small vecs.
#define XPAD 68  // 64 nodes padded to 68 (mult of 4 for float4 reads)

__global__ void __launch_bounds__(256, 2)
gcn_kernel(const float* __restrict__ x,
           const float* __restrict__ bz,
           const float* __restrict__ bh,
           const float* __restrict__ wlin,
           const float* __restrict__ blin,
           float* __restrict__ out) {
    extern __shared__ float smem[];
    float* sWz = smem;                       // 128*64
    float* sWh = smem + F_IN * HID;          // 128*64
    float* sX  = sWh + F_IN * HID;           // 128*XPAD, layout sX[k][node]
    float* sBz = sX + F_IN * XPAD;           // 64
    float* sBh = sBz + HID;                  // 64
    float* sWl = sBh + HID;                  // 64

    const int tid = threadIdx.x;
    const int tx = tid & 15;      // output-col group
    const int ty = tid >> 4;      // node group

    // Stage weights (coalesced).
    #pragma unroll
    for (int i = tid; i < F_IN * HID; i += 256) {
        sWz[i] = g_Wz[i];
        sWh[i] = g_Wh[i];
    }
    if (tid < HID) {
        sBz[tid] = bz[tid];
        sBh[tid] = bh[tid];
        sWl[tid] = wlin[tid];
    }

    const int node0 = blockIdx.x * 64;

    // Stage x tile transposed: sX[k][node_local]. Consecutive threads read
    // consecutive k within a node row -> coalesced LDG.
    for (int i = tid; i < 64 * F_IN; i += 256) {
        int nl = i >> 7;          // node_local
        int k  = i & 127;
        int node = node0 + nl;
        float v = (node < N_NODES) ? x[node * F_IN + k] : 0.0f;
        sX[k * XPAD + nl] = v;
    }
    __syncthreads();

    float az[4][4], ah[4][4];
    #pragma unroll
    for (int r = 0; r < 4; r++)
        #pragma unroll
        for (int c = 0; c < 4; c++) { az[r][c] = 0.0f; ah[r][c] = 0.0f; }

    // Main loop: 128 k-steps, 32 FMAs + 3x LDS.128 each.
    #pragma unroll 4
    for (int k = 0; k < F_IN; k++) {
        float4 a  = *reinterpret_cast<const float4*>(&sX[k * XPAD + ty * 4]);
        float4 wz = *reinterpret_cast<const float4*>(&sWz[k * HID + tx * 4]);
        float4 wh = *reinterpret_cast<const float4*>(&sWh[k * HID + tx * 4]);
        float av[4] = {a.x, a.y, a.z, a.w};
        float zv[4] = {wz.x, wz.y, wz.z, wz.w};
        float hv[4] = {wh.x, wh.y, wh.z, wh.w};
        #pragma unroll
        for (int r = 0; r < 4; r++)
            #pragma unroll
            for (int c = 0; c < 4; c++) {
                az[r][c] = fmaf(av[r], zv[c], az[r][c]);
                ah[r][c] = fmaf(av[r], hv[c], ah[r][c]);
            }
    }

    // Fused epilogue: h = relu((1 - sigmoid(az+bz)) * tanh(ah+bh));
    // partial = sum_c h * wlin[c]. Note 1 - sigmoid(t) = 1/(1+exp(t)).
    float p[4] = {0.0f, 0.0f, 0.0f, 0.0f};
    #pragma unroll
    for (int r = 0; r < 4; r++) {
        #pragma unroll
        for (int c = 0; c < 4; c++) {
            int j = tx * 4 + c;
            float one_minus_z = 1.0f / (1.0f + expf(az[r][c] + sBz[j]));
            float ht = tanhf(ah[r][c] + sBh[j]);
            float h = one_minus_z * ht;
            h = fmaxf(h, 0.0f);
            p[r] = fmaf(h, sWl[j], p[r]);
        }
    }

    // Reduce the 16 col-group partials per node (half-warp shuffle: lanes with
    // the same ty sit in a contiguous 16-lane group within the warp).
    #pragma unroll
    for (int off = 8; off > 0; off >>= 1) {
        #pragma unroll
        for (int r = 0; r < 4; r++)
            p[r] += __shfl_down_sync(0xffffffffu, p[r], off, 16);
    }

    if (tx == 0) {
        float bl = blin[0];
        #pragma unroll
        for (int r = 0; r < 4; r++) {
            int node = node0 + ty * 4 + r;
            if (node < N_NODES) out[node] = p[r] + bl;
        }
    }
}

extern "C" void kernel_launch(void* const* d_in, const int* in_sizes, int n_in,
                              void* d_out, int out_size) {
    // metadata order: x, edge_index, edge_weight, Wz, bz, Wr, br, Wh, bh, Wlin, blin
    const float* x    = (const float*)d_in[0];
    const float* Wz   = (const float*)d_in[3];
    const float* bz   = (const float*)d_in[4];
    const float* Wh   = (const float*)d_in[7];
    const float* bh   = (const float*)d_in[8];
    const float* wlin = (const float*)d_in[9];
    const float* blin = (const float*)d_in[10];
    float* out = (float*)d_out;

    prep_kernel<<<(F_IN * HID + 255) / 256, 256>>>(Wz, Wh);

    size_t smem_bytes = (size_t)(2 * F_IN * HID + F_IN * XPAD + 3 * HID) * sizeof(float);
    cudaFuncSetAttribute(gcn_kernel, cudaFuncAttributeMaxDynamicSharedMemorySize,
                         (int)smem_bytes);
    int grid = (N_NODES + 63) / 64;
    gcn_kernel<<<grid, 256, smem_bytes>>>(x, bz, bh, wlin, blin, out);
}